// round 10
// baseline (speedup 1.0000x reference)
#include <cuda_runtime.h>
#include <cstdint>
#include <cfloat>

#define N_NODES_MAX 100000
#define N_EDGES_MAX 1600000
#define FULL 0xFFFFFFFFu

typedef unsigned long long ull;

// ---------------- scratch (static device globals) ---------------------------
__device__ float4  g_h[N_NODES_MAX * 16];     // [N,64] projected features
__device__ float4  g_el[N_NODES_MAX];         // [N,4]
__device__ float4  g_er[N_NODES_MAX];         // [N,4]
__device__ int     g_cnt[N_NODES_MAX];        // in-degree
__device__ int     g_fill[N_NODES_MAX];       // scatter cursors
__device__ int     g_rowptr[N_NODES_MAX];     // exclusive prefix of cnt
__device__ int     g_blksum[128];
__device__ int     g_esrc[N_EDGES_MAX];       // CSR: src node per slot

__device__ __forceinline__ float leaky(float x) { return x > 0.f ? x : 0.2f * x; }

__device__ __forceinline__ ull pack2(float f) {
    ull r;
    asm("mov.b64 %0, {%1, %1};" : "=l"(r) : "f"(f));
    return r;
}
__device__ __forceinline__ void fma2(ull& acc, ull a, ull b) {
    asm("fma.rn.f32x2 %0, %1, %2, %0;" : "+l"(acc) : "l"(a), "l"(b));
}
__device__ __forceinline__ void unpack2(ull v, float& lo, float& hi) {
    asm("mov.b64 {%0, %1}, %2;" : "=f"(lo), "=f"(hi) : "l"(v));
}

// ---------------- kernel: zero counters -------------------------------------
__global__ void zero_kernel(int n_nodes) {
    int i = blockIdx.x * blockDim.x + threadIdx.x;
    if (i < n_nodes) { g_cnt[i] = 0; g_fill[i] = 0; }
}

// ---------------- kernel: in-degree histogram -------------------------------
__global__ void hist_kernel(const int* __restrict__ dst, int n_edges) {
    int e = blockIdx.x * blockDim.x + threadIdx.x;
    if (e < n_edges) atomicAdd(&g_cnt[dst[e]], 1);
}

// ---------------- scan: rowptr = exclusive_scan(cnt) ------------------------
__global__ __launch_bounds__(1024) void scan1_kernel(int n) {
    __shared__ int sh[1024];
    int i = blockIdx.x * 1024 + threadIdx.x;
    int v = (i < n) ? g_cnt[i] : 0;
    sh[threadIdx.x] = v;
    __syncthreads();
    for (int off = 1; off < 1024; off <<= 1) {
        int t = (threadIdx.x >= off) ? sh[threadIdx.x - off] : 0;
        __syncthreads();
        sh[threadIdx.x] += t;
        __syncthreads();
    }
    if (i < n) g_rowptr[i] = sh[threadIdx.x] - v;
    if (threadIdx.x == 1023) g_blksum[blockIdx.x] = sh[1023];
}
// merged scan2+scan3: each block computes prefix of blksum below it, adds.
__global__ __launch_bounds__(1024) void scan23_kernel(int n, int nb) {
    __shared__ int sh[128];
    const int t = threadIdx.x;
    if (t < 128) sh[t] = (t < nb && t < (int)blockIdx.x) ? g_blksum[t] : 0;
    __syncthreads();
    if (t < 64)  sh[t] += sh[t + 64];
    __syncthreads();
    if (t < 32) {
        int v = sh[t] + sh[t + 32];
#pragma unroll
        for (int o = 16; o; o >>= 1) v += __shfl_xor_sync(FULL, v, o);
        if (t == 0) sh[0] = v;
    }
    __syncthreads();
    const int off = sh[0];
    int i = blockIdx.x * 1024 + t;
    if (i < n) g_rowptr[i] += off;
}

// ---------------- kernel: CSR scatter ----------------------------------------
__global__ void scatter_kernel(const int* __restrict__ src,
                               const int* __restrict__ dst, int n_edges) {
    int e = blockIdx.x * blockDim.x + threadIdx.x;
    if (e >= n_edges) return;
    int d = dst[e];
    int r = atomicAdd(&g_fill[d], 1);
    g_esrc[g_rowptr[d] + r] = src[e];
}

// ---------------- kernel: h = feat @ W, el/er (wide tile, f32x2) -------------
// 128 threads; tile = 128 nodes x 64 cols. Thread (tx=tid&31, ty=tid>>5) owns
// nodes tx*4..+3 and cols ty*16..+15 (= whole head ty). featT staged in 32-k
// chunks (16KB). Per warp-k: 8 LDS wavefronts for 32 FFMA2.
#define FEATT_F   (32 * 128)
#define GEMM_SMEM_FLOATS (FEATT_F + 128 * 64 + 64 + 64 + 512 + 512)
__global__ __launch_bounds__(128, 4)
void gemm_kernel(const float* __restrict__ feat, const float* __restrict__ W,
                 const float* __restrict__ attn_l, const float* __restrict__ attn_r,
                 int n_nodes) {
    extern __shared__ float smem[];
    float* featT = smem;                       // [k%32][node] 32x128
    float* Wsh   = smem + FEATT_F;             // [k][col]  128x64
    float* alS   = Wsh + 8192;                 // 64
    float* arS   = alS + 64;                   // 64
    float* elS   = arS + 64;                   // [node][head] 128x4
    float* erS   = elS + 512;                  // 128x4

    const int tid  = threadIdx.x;
    const int tx   = tid & 31;
    const int ty   = tid >> 5;                 // 0..3 = head
    const int base = blockIdx.x * 128;

    for (int i = tid; i < 128 * 64; i += 128) Wsh[i] = W[i];
    if (tid < 64) { alS[tid] = attn_l[tid]; arS[tid] = attn_r[tid]; }

    ull acc2[32];
#pragma unroll
    for (int j = 0; j < 32; j++) acc2[j] = 0ull;

    const float4* feat4 = (const float4*)feat;
    const int node_s = base + tid;             // staging: one node per thread

    for (int c = 0; c < 4; c++) {
        if (c) __syncthreads();
        // stage chunk c: thread stages its node's 8 float4 (32 k values)
#pragma unroll
        for (int j = 0; j < 8; j++) {
            float4 v = (node_s < n_nodes)
                         ? feat4[node_s * 32 + c * 8 + j]
                         : make_float4(0.f, 0.f, 0.f, 0.f);
            featT[(j * 4 + 0) * 128 + tid] = v.x;
            featT[(j * 4 + 1) * 128 + tid] = v.y;
            featT[(j * 4 + 2) * 128 + tid] = v.z;
            featT[(j * 4 + 3) * 128 + tid] = v.w;
        }
        __syncthreads();

#pragma unroll 4
        for (int k = 0; k < 32; k++) {
            float4 f = *(const float4*)&featT[k * 128 + tx * 4];
            ull fd0 = pack2(f.x), fd1 = pack2(f.y);
            ull fd2 = pack2(f.z), fd3 = pack2(f.w);
            const ulonglong2* Wv =
                (const ulonglong2*)&Wsh[(c * 32 + k) * 64 + ty * 16];
            ulonglong2 wa = Wv[0];   // cols +0..3  (2 pairs)
            ulonglong2 wb = Wv[1];   // cols +4..7
            ulonglong2 wc = Wv[2];   // cols +8..11
            ulonglong2 wd = Wv[3];   // cols +12..15
            fma2(acc2[0],  fd0, wa.x); fma2(acc2[1],  fd0, wa.y);
            fma2(acc2[2],  fd0, wb.x); fma2(acc2[3],  fd0, wb.y);
            fma2(acc2[4],  fd0, wc.x); fma2(acc2[5],  fd0, wc.y);
            fma2(acc2[6],  fd0, wd.x); fma2(acc2[7],  fd0, wd.y);
            fma2(acc2[8],  fd1, wa.x); fma2(acc2[9],  fd1, wa.y);
            fma2(acc2[10], fd1, wb.x); fma2(acc2[11], fd1, wb.y);
            fma2(acc2[12], fd1, wc.x); fma2(acc2[13], fd1, wc.y);
            fma2(acc2[14], fd1, wd.x); fma2(acc2[15], fd1, wd.y);
            fma2(acc2[16], fd2, wa.x); fma2(acc2[17], fd2, wa.y);
            fma2(acc2[18], fd2, wb.x); fma2(acc2[19], fd2, wb.y);
            fma2(acc2[20], fd2, wc.x); fma2(acc2[21], fd2, wc.y);
            fma2(acc2[22], fd2, wd.x); fma2(acc2[23], fd2, wd.y);
            fma2(acc2[24], fd3, wa.x); fma2(acc2[25], fd3, wa.y);
            fma2(acc2[26], fd3, wb.x); fma2(acc2[27], fd3, wb.y);
            fma2(acc2[28], fd3, wc.x); fma2(acc2[29], fd3, wc.y);
            fma2(acc2[30], fd3, wd.x); fma2(acc2[31], fd3, wd.y);
        }
    }

    float o[4][16];
#pragma unroll
    for (int n = 0; n < 4; n++)
#pragma unroll
        for (int cp = 0; cp < 8; cp++)
            unpack2(acc2[n * 8 + cp], o[n][2 * cp], o[n][2 * cp + 1]);

    // el/er: thread's 16 cols = whole head ty -> complete dot, plain STS
#pragma unroll
    for (int n = 0; n < 4; n++) {
        float sl = 0.f, sr = 0.f;
#pragma unroll
        for (int cc = 0; cc < 16; cc++) {
            sl += o[n][cc] * alS[ty * 16 + cc];
            sr += o[n][cc] * arS[ty * 16 + cc];
        }
        int node_l = tx * 4 + n;
        elS[node_l * 4 + ty] = sl;
        erS[node_l * 4 + ty] = sr;
    }

    // store h (four STG.128 per node)
    float* g_h_f = (float*)g_h;
#pragma unroll
    for (int n = 0; n < 4; n++) {
        int node = base + tx * 4 + n;
        if (node < n_nodes) {
            float* p = g_h_f + node * 64 + ty * 16;
#pragma unroll
            for (int j = 0; j < 4; j++)
                *(float4*)(p + 4 * j) = make_float4(o[n][4 * j + 0], o[n][4 * j + 1],
                                                    o[n][4 * j + 2], o[n][4 * j + 3]);
        }
    }

    __syncthreads();
    {
        int node = base + tid;
        if (node < n_nodes) {
            g_el[node] = ((const float4*)elS)[tid];
            g_er[node] = ((const float4*)erS)[tid];
        }
    }
}

// ---------------- kernel: fused softmax + aggregation ------------------------
// one warp per node. ex computed lane-parallel (1 edge per lane), staged in
// smem; serial agg loop = shfl(s) + LDS(ex) + LDG(h) + 2 FFMA per edge.
__global__ __launch_bounds__(256)
void node_kernel(const float* __restrict__ bias, float* __restrict__ out,
                 int n_nodes) {
    __shared__ float sm_ex[8][128];   // [warp][edge*4 + head]
    const int gwarp = (blockIdx.x * blockDim.x + threadIdx.x) >> 5;
    const int w     = (threadIdx.x >> 5);
    const int lane  = threadIdx.x & 31;
    if (gwarp >= n_nodes) return;

    const int base = g_rowptr[gwarp];
    const int deg  = g_cnt[gwarp];
    const int hd   = lane >> 3;

    const float2 b2 = ((const float2*)bias)[lane];
    float2* outp = (float2*)out + (gwarp * 32 + lane);
    if (deg == 0) { *outp = b2; return; }

    const float4 er4 = g_er[gwarp];
    const float2* h2 = (const float2*)g_h;

    float2 acc  = make_float2(0.f, 0.f);
    float4 den4 = make_float4(0.f, 0.f, 0.f, 0.f);

    const int nb = (deg + 31) >> 5;
    int s_reg = (lane < deg) ? g_esrc[base + lane] : 0;
    for (int b = 0; b < nb; b++) {
        const int cur = s_reg;
        const int cnt = min(32, deg - b * 32);
        const int noff = (b + 1) * 32;
        if (b + 1 < nb)
            s_reg = (noff + lane < deg) ? g_esrc[base + noff + lane] : 0;

        float4 ex = make_float4(0.f, 0.f, 0.f, 0.f);
        if (lane < cnt) {
            float4 a = g_el[cur];
            ex.x = __expf(leaky(a.x + er4.x));
            ex.y = __expf(leaky(a.y + er4.y));
            ex.z = __expf(leaky(a.z + er4.z));
            ex.w = __expf(leaky(a.w + er4.w));
        }
        den4.x += ex.x; den4.y += ex.y; den4.z += ex.z; den4.w += ex.w;
        __syncwarp();
        ((float4*)sm_ex[w])[lane] = ex;
        __syncwarp();

#pragma unroll 8
        for (int i = 0; i < cnt; i++) {
            int s = __shfl_sync(FULL, cur, i);
            float a = sm_ex[w][i * 4 + hd];
            float2 v = h2[s * 32 + lane];
            acc.x += a * v.x;
            acc.y += a * v.y;
        }
    }

#pragma unroll
    for (int o = 16; o; o >>= 1) {
        den4.x += __shfl_xor_sync(FULL, den4.x, o);
        den4.y += __shfl_xor_sync(FULL, den4.y, o);
        den4.z += __shfl_xor_sync(FULL, den4.z, o);
        den4.w += __shfl_xor_sync(FULL, den4.w, o);
    }
    const float den = hd == 0 ? den4.x : hd == 1 ? den4.y : hd == 2 ? den4.z : den4.w;
    const float rd = 1.f / den;
    *outp = make_float2(acc.x * rd + b2.x, acc.y * rd + b2.y);
}

// ---------------- launcher --------------------------------------------------
extern "C" void kernel_launch(void* const* d_in, const int* in_sizes, int n_in,
                              void* d_out, int out_size) {
    const float* feat   = (const float*)d_in[0];
    const float* W      = (const float*)d_in[1];
    const float* attn_l = (const float*)d_in[2];
    const float* attn_r = (const float*)d_in[3];
    const float* bias   = (const float*)d_in[4];
    const int*   src    = (const int*)d_in[5];
    const int*   dst    = (const int*)d_in[6];
    float*       out    = (float*)d_out;

    const int n_nodes = in_sizes[0] / 128;
    const int n_edges = in_sizes[5];
    const int nb      = (n_nodes + 1023) / 1024;

    cudaFuncSetAttribute(gemm_kernel, cudaFuncAttributeMaxDynamicSharedMemorySize,
                         GEMM_SMEM_FLOATS * (int)sizeof(float));

    // gemm placed 4th: ncu captures launch #4
    zero_kernel<<<(n_nodes + 255) / 256, 256>>>(n_nodes);
    hist_kernel<<<(n_edges + 255) / 256, 256>>>(dst, n_edges);
    scan1_kernel<<<nb, 1024>>>(n_nodes);
    gemm_kernel<<<(n_nodes + 127) / 128, 128,
                  GEMM_SMEM_FLOATS * (int)sizeof(float)>>>(feat, W, attn_l,
                                                           attn_r, n_nodes);
    scan23_kernel<<<nb, 1024>>>(n_nodes, nb);
    scatter_kernel<<<(n_edges + 255) / 256, 256>>>(src, dst, n_edges);
    node_kernel<<<(n_nodes * 32 + 255) / 256, 256>>>(bias, out, n_nodes);
}